// round 2
// baseline (speedup 1.0000x reference)
#include <cuda_runtime.h>
#include <cstdint>
#include <cstdio>

#define NN 50000
#define EE 1600000
#define RR 8
#define HH 8

// ---------------- scratch (device globals; no allocations allowed) ----------
__device__ float g_q[(size_t)NN * 128];
__device__ float g_k[(size_t)NN * 128];
__device__ float g_v[(size_t)NN * 128];
__device__ float g_krel[(size_t)RR * NN * 128];   // [r][n][h*16+e]
__device__ float g_useg[(size_t)NN * RR * 128];   // [n][r][h*16+d] raw ex-weighted v sums
__device__ float g_ex[(size_t)EE * HH];
__device__ float g_den[(size_t)NN * RR * HH];
__device__ float g_coef[(size_t)NN * RR * HH];
__device__ float g_t[(size_t)NN * 128];

// ---------------- helpers ---------------------------------------------------
__device__ __forceinline__ unsigned long long pack2(float a) {
    unsigned long long r;
    asm("mov.b64 %0, {%1, %1};" : "=l"(r) : "f"(a));
    return r;
}
__device__ __forceinline__ unsigned long long fma2(unsigned long long a,
                                                   unsigned long long b,
                                                   unsigned long long c) {
    unsigned long long d;
    asm("fma.rn.f32x2 %0, %1, %2, %3;" : "=l"(d) : "l"(a), "l"(b), "l"(c));
    return d;
}
__device__ __forceinline__ void unpack2(unsigned long long a, float& lo, float& hi) {
    asm("mov.b64 {%0, %1}, %2;" : "=f"(lo), "=f"(hi) : "l"(a));
}

// ---------------- K0: zero accumulators -------------------------------------
__global__ void zero_kernel() {
    size_t i = (size_t)blockIdx.x * blockDim.x + threadIdx.x;
    size_t stride = (size_t)gridDim.x * blockDim.x;
    const size_t nd = (size_t)NN * RR * HH;
    for (size_t j = i; j < nd; j += stride) g_den[j] = 0.f;
    float4* u4 = (float4*)g_useg;
    const size_t nu = (size_t)NN * RR * 32;   // float4 count
    const float4 z = make_float4(0.f, 0.f, 0.f, 0.f);
    for (size_t j = i; j < nu; j += stride) u4[j] = z;
}

// ---------------- K1/K5: tiled GEMM  Y = X @ W^T + b  (optional skip epi) ----
// X: [NN,128], W: [128,128], row-major. mode=1: Y = a*(XW^T+b) + (1-a)*dsth
// f32x2-packed accumulators: each thread owns 4 rows x 8 cols (4 col-pairs).
#define GEMM_SMEM ((128 * 132 + 64 * 129) * 4)
__global__ void gemm128_kernel(const float* __restrict__ X,
                               const float* __restrict__ W,
                               const float* __restrict__ bias,
                               float* __restrict__ Y,
                               const float* __restrict__ dsth,
                               const float* __restrict__ skipv,
                               int mode) {
    extern __shared__ float sm[];
    float* Wt = sm;                 // [128][132]  Wt[i][o] = W[o][i]
    float* Xs = sm + 128 * 132;     // [64][129]
    const int tid = threadIdx.x;    // 256 threads
    const int row0 = blockIdx.x * 64;

#pragma unroll
    for (int kk = 0; kk < 64; kk++) {
        int idx = kk * 256 + tid;                 // o = idx>>7, i = idx&127
        Wt[(idx & 127) * 132 + (idx >> 7)] = W[idx];
    }
#pragma unroll
    for (int kk = 0; kk < 32; kk++) {
        int idx = kk * 256 + tid;
        int r = idx >> 7, i = idx & 127;
        int row = row0 + r;
        Xs[r * 129 + i] = (row < NN) ? X[(size_t)row * 128 + i] : 0.f;
    }
    __syncthreads();

    const int tx = tid & 15, ty = tid >> 4;
    const int cb = tx * 8;
    unsigned long long acc2[4][4];
#pragma unroll
    for (int a = 0; a < 4; a++)
#pragma unroll
        for (int b = 0; b < 4; b++) acc2[a][b] = 0ull;

#pragma unroll 4
    for (int i = 0; i < 128; i++) {
        const unsigned long long* wp =
            (const unsigned long long*)&Wt[i * 132 + cb];
        unsigned long long w0 = wp[0], w1 = wp[1], w2 = wp[2], w3 = wp[3];
#pragma unroll
        for (int rr = 0; rr < 4; rr++) {
            unsigned long long xv2 = pack2(Xs[(ty * 4 + rr) * 129 + i]);
            acc2[rr][0] = fma2(xv2, w0, acc2[rr][0]);
            acc2[rr][1] = fma2(xv2, w1, acc2[rr][1]);
            acc2[rr][2] = fma2(xv2, w2, acc2[rr][2]);
            acc2[rr][3] = fma2(xv2, w3, acc2[rr][3]);
        }
    }

    float alpha = 1.f, beta = 0.f;
    if (mode) {
        float s = skipv[0];
        alpha = 1.f / (1.f + __expf(-s));
        beta = 1.f - alpha;
    }
#pragma unroll
    for (int rr = 0; rr < 4; rr++) {
        int row = row0 + ty * 4 + rr;
        if (row < NN) {
#pragma unroll
            for (int j = 0; j < 4; j++) {
                float lo, hi;
                unpack2(acc2[rr][j], lo, hi);
                int o = cb + 2 * j;
                float v0 = lo + bias[o];
                float v1 = hi + bias[o + 1];
                if (mode) {
                    v0 = alpha * v0 + beta * dsth[(size_t)row * 128 + o];
                    v1 = alpha * v1 + beta * dsth[(size_t)row * 128 + o + 1];
                }
                Y[(size_t)row * 128 + o] = v0;
                Y[(size_t)row * 128 + o + 1] = v1;
            }
        }
    }
}

// ---------------- K2: relation transform (k_rel only) -----------------------
// Lane-per-node; per head: pack k_d into f32x2, FFMA2 over e-pairs with
// broadcast LDS.64 of A[d][2e..2e+1]. rel_att resident in smem (64 KB).
#define RT_SMEM (16384 * 4)
__global__ void reltrans_kernel(const float* __restrict__ ratt) {
    extern __shared__ float sm[];   // [8][8][16][16]
    for (int i = threadIdx.x; i < 16384; i += 256) sm[i] = ratt[i];
    __syncthreads();

    const int lane = threadIdx.x & 31;
    const int wid = blockIdx.x * 8 + (threadIdx.x >> 5);
    const int nwarps = gridDim.x * 8;
    const int ntiles = (NN + 31) / 32;

    for (int tile = wid; tile < ntiles; tile += nwarps) {
        const int n = tile * 32 + lane;
        const bool valid = n < NN;
#pragma unroll 1
        for (int h = 0; h < 8; h++) {
            float kh[16];
            if (valid) {
                const float4* ip = (const float4*)(g_k + (size_t)n * 128 + h * 16);
#pragma unroll
                for (int j = 0; j < 4; j++) {
                    float4 t4 = ip[j];
                    kh[4 * j] = t4.x; kh[4 * j + 1] = t4.y;
                    kh[4 * j + 2] = t4.z; kh[4 * j + 3] = t4.w;
                }
            } else {
#pragma unroll
                for (int j = 0; j < 16; j++) kh[j] = 0.f;
            }
            unsigned long long kd2[16];
#pragma unroll
            for (int d = 0; d < 16; d++) kd2[d] = pack2(kh[d]);

#pragma unroll 1
            for (int r = 0; r < 8; r++) {
                unsigned long long acc2[8];
#pragma unroll
                for (int ep = 0; ep < 8; ep++) acc2[ep] = 0ull;
                const unsigned long long* ap =
                    (const unsigned long long*)(sm + ((r * 8 + h) << 8));
#pragma unroll
                for (int d = 0; d < 16; d++) {
#pragma unroll
                    for (int ep = 0; ep < 8; ep++)
                        acc2[ep] = fma2(kd2[d], ap[d * 8 + ep], acc2[ep]);
                }
                if (valid) {
                    unsigned long long* op = (unsigned long long*)
                        (g_krel + ((size_t)r * NN + n) * 128 + h * 16);
#pragma unroll
                    for (int ep = 0; ep < 8; ep++) op[ep] = acc2[ep];
                }
            }
        }
    }
}

// ---------------- K3: edge attention (no-max softmax numerator) -------------
// warp per edge: att[h] = (q[dst] . k_rel[r][src])_h * pri[r,h]/4 ; ex=exp.
__global__ void edge_att_kernel(const int* __restrict__ src_idx,
                                const int* __restrict__ dst_idx,
                                const int* __restrict__ etype,
                                const float* __restrict__ pri) {
    const int e = blockIdx.x * 8 + (threadIdx.x >> 5);
    const int lane = threadIdx.x & 31;
    const int s = __ldg(&src_idx[e]);
    const int d = __ldg(&dst_idx[e]);
    const int r = __ldg(&etype[e]);
    const float4 qv = *(const float4*)&g_q[(size_t)d * 128 + lane * 4];
    const float4 kv = *(const float4*)&g_krel[((size_t)r * NN + s) * 128 + lane * 4];
    float p = qv.x * kv.x + qv.y * kv.y + qv.z * kv.z + qv.w * kv.w;
    p += __shfl_xor_sync(0xffffffffu, p, 1);
    p += __shfl_xor_sync(0xffffffffu, p, 2);
    const int h = lane >> 2;
    const float ex = __expf(p * __ldg(&pri[r * 8 + h]) * 0.25f);
    if ((lane & 3) == 0) {
        g_ex[(size_t)e * 8 + h] = ex;
        atomicAdd(&g_den[((size_t)d * RR + r) * 8 + h], ex);
    }
}

// ---------------- K3.5: per-(node,rel,head) coefficient ---------------------
// coef = present ? 1/(den * n_rel) : 0 ; presence = den > 0 (== cnt>0).
__global__ void coef_kernel() {
    int n = blockIdx.x * 256 + threadIdx.x;
    if (n >= NN) return;
    int cnt = 0;
    float d0[8];
#pragma unroll
    for (int r = 0; r < 8; r++) {
        d0[r] = g_den[((size_t)n * RR + r) * 8];
        cnt += (d0[r] > 0.f);
    }
    float invn = 1.f / (float)(cnt > 0 ? cnt : 1);
#pragma unroll
    for (int r = 0; r < 8; r++) {
        size_t base = ((size_t)n * RR + r) * 8;
        if (d0[r] > 0.f) {
#pragma unroll
            for (int hh = 0; hh < 8; hh++) g_coef[base + hh] = invn / g_den[base + hh];
        } else {
#pragma unroll
            for (int hh = 0; hh < 8; hh++) g_coef[base + hh] = 0.f;
        }
    }
}

// ---------------- K4: edge aggregation of raw v into u_seg ------------------
// u_seg[d][r][h][:] += ex * v[s][h][:]  (gathers v: 25 MB, L2-resident)
__global__ void edge_agg_kernel(const int* __restrict__ src_idx,
                                const int* __restrict__ dst_idx,
                                const int* __restrict__ etype) {
    const int e = blockIdx.x * 8 + (threadIdx.x >> 5);
    const int lane = threadIdx.x & 31;
    const int s = __ldg(&src_idx[e]);
    const int d = __ldg(&dst_idx[e]);
    const int r = __ldg(&etype[e]);
    const int h = lane >> 2;
    const float w = g_ex[(size_t)e * 8 + h];
    const float4 vv = *(const float4*)&g_v[(size_t)s * 128 + lane * 4];
    float* up = &g_useg[((size_t)d * RR + r) * 128 + lane * 4];
    asm volatile("red.global.add.v4.f32 [%0], {%1, %2, %3, %4};"
                 :: "l"(up), "f"(w * vv.x), "f"(w * vv.y),
                    "f"(w * vv.z), "f"(w * vv.w)
                 : "memory");
}

// ---------------- K4.5: post transform  t[n] = sum_r coef*(u_seg@rel_msg) ---
// warp per node: lane handles (h = lane>>2, 4 output dims at (lane&3)*4).
#define PT_SMEM (16384 * 4)
__global__ void post_kernel(const float* __restrict__ rmsg) {
    extern __shared__ float sm[];   // [8][8][16][16]
    for (int i = threadIdx.x; i < 16384; i += 256) sm[i] = rmsg[i];
    __syncthreads();

    const int lane = threadIdx.x & 31;
    const int n = blockIdx.x * 8 + (threadIdx.x >> 5);
    if (n >= NN) return;
    const int h = lane >> 2;
    const int q4 = lane & 3;

    unsigned long long acc2[2] = {0ull, 0ull};
#pragma unroll 1
    for (int r = 0; r < 8; r++) {
        const float4* up = (const float4*)
            (g_useg + ((size_t)n * RR + r) * 128 + h * 16);
        float uh[16];
#pragma unroll
        for (int j = 0; j < 4; j++) {
            float4 t4 = up[j];
            uh[4 * j] = t4.x; uh[4 * j + 1] = t4.y;
            uh[4 * j + 2] = t4.z; uh[4 * j + 3] = t4.w;
        }
        unsigned long long ud2[16];
#pragma unroll
        for (int d = 0; d < 16; d++) ud2[d] = pack2(uh[d]);

        const unsigned long long* mp =
            (const unsigned long long*)(sm + ((r * 8 + h) << 8));
        unsigned long long p2[2] = {0ull, 0ull};
#pragma unroll
        for (int d = 0; d < 16; d++) {
            p2[0] = fma2(ud2[d], mp[d * 8 + q4 * 2], p2[0]);
            p2[1] = fma2(ud2[d], mp[d * 8 + q4 * 2 + 1], p2[1]);
        }
        const unsigned long long c2 =
            pack2(g_coef[((size_t)n * RR + r) * 8 + h]);
        acc2[0] = fma2(c2, p2[0], acc2[0]);
        acc2[1] = fma2(c2, p2[1], acc2[1]);
    }
    float4 outv;
    unpack2(acc2[0], outv.x, outv.y);
    unpack2(acc2[1], outv.z, outv.w);
    *(float4*)(g_t + (size_t)n * 128 + h * 16 + q4 * 4) = outv;
}

// ---------------- host ------------------------------------------------------
extern "C" void kernel_launch(void* const* d_in, const int* in_sizes, int n_in,
                              void* d_out, int out_size) {
    const float* src_h   = (const float*)d_in[0];
    const float* dst_h   = (const float*)d_in[1];
    const float* Wk      = (const float*)d_in[2];
    const float* bk      = (const float*)d_in[3];
    const float* Wq      = (const float*)d_in[4];
    const float* bq      = (const float*)d_in[5];
    const float* Wv      = (const float*)d_in[6];
    const float* bv      = (const float*)d_in[7];
    const float* Wa      = (const float*)d_in[8];
    const float* ba      = (const float*)d_in[9];
    const float* rel_pri = (const float*)d_in[10];
    const float* rel_att = (const float*)d_in[11];
    const float* rel_msg = (const float*)d_in[12];
    const float* skip    = (const float*)d_in[13];
    const int* src_idx   = (const int*)d_in[14];
    const int* dst_idx   = (const int*)d_in[15];
    const int* edge_type = (const int*)d_in[16];
    float* out = (float*)d_out;

    cudaFuncSetAttribute(gemm128_kernel,
                         cudaFuncAttributeMaxDynamicSharedMemorySize, GEMM_SMEM);
    cudaFuncSetAttribute(reltrans_kernel,
                         cudaFuncAttributeMaxDynamicSharedMemorySize, RT_SMEM);
    cudaFuncSetAttribute(post_kernel,
                         cudaFuncAttributeMaxDynamicSharedMemorySize, PT_SMEM);

    float *p_q, *p_k, *p_v, *p_t;
    cudaGetSymbolAddress((void**)&p_q, g_q);
    cudaGetSymbolAddress((void**)&p_k, g_k);
    cudaGetSymbolAddress((void**)&p_v, g_v);
    cudaGetSymbolAddress((void**)&p_t, g_t);

    const int gblocks = (NN + 63) / 64;

    zero_kernel<<<2048, 256>>>();
    gemm128_kernel<<<gblocks, 256, GEMM_SMEM>>>(src_h, Wk, bk, p_k, nullptr, nullptr, 0);
    gemm128_kernel<<<gblocks, 256, GEMM_SMEM>>>(src_h, Wv, bv, p_v, nullptr, nullptr, 0);
    gemm128_kernel<<<gblocks, 256, GEMM_SMEM>>>(dst_h, Wq, bq, p_q, nullptr, nullptr, 0);
    reltrans_kernel<<<196, 256, RT_SMEM>>>(rel_att);
    edge_att_kernel<<<EE / 8, 256>>>(src_idx, dst_idx, edge_type, rel_pri);
    coef_kernel<<<(NN + 255) / 256, 256>>>();
    edge_agg_kernel<<<EE / 8, 256>>>(src_idx, dst_idx, edge_type);
    post_kernel<<<(NN + 7) / 8, 256, PT_SMEM>>>(rel_msg);
    gemm128_kernel<<<gblocks, 256, GEMM_SMEM>>>(p_t, Wa, ba, out, dst_h, skip, 1);
}

// round 16
// speedup vs baseline: 1.1177x; 1.1177x over previous
#include <cuda_runtime.h>
#include <cstdint>

#define NN 50000
#define EE 1600000
#define RR 8
#define HH 8
#define NKEY (NN * RR)
#define CAP 96

// ---------------- scratch (device globals; no allocations allowed) ----------
__device__ float g_q[(size_t)NN * 128];
__device__ float g_k[(size_t)NN * 128];
__device__ float g_v[(size_t)NN * 128];
__device__ float g_krel[(size_t)RR * NN * 128];   // [r][n][h*16+e]
__device__ float g_t[(size_t)NN * 128];
__device__ unsigned g_hist[NKEY];                 // histogram, then scatter cursor
__device__ unsigned g_keyoff[NKEY + 1];
__device__ unsigned g_bsum[256];
__device__ unsigned g_rec[EE];                    // src | (r<<16), sorted by dst*8+r

// ---------------- helpers ---------------------------------------------------
__device__ __forceinline__ unsigned long long pack2(float a) {
    unsigned long long r;
    asm("mov.b64 %0, {%1, %1};" : "=l"(r) : "f"(a));
    return r;
}
__device__ __forceinline__ unsigned long long fma2(unsigned long long a,
                                                   unsigned long long b,
                                                   unsigned long long c) {
    unsigned long long d;
    asm("fma.rn.f32x2 %0, %1, %2, %3;" : "=l"(d) : "l"(a), "l"(b), "l"(c));
    return d;
}
__device__ __forceinline__ void unpack2(unsigned long long a, float& lo, float& hi) {
    asm("mov.b64 {%0, %1}, %2;" : "=f"(lo), "=f"(hi) : "l"(a));
}

// ---------------- K: zero histogram ----------------------------------------
__global__ void zero_hist_kernel() {
    int i = blockIdx.x * 256 + threadIdx.x;
    if (i < NKEY) g_hist[i] = 0u;
}

// ---------------- K: histogram over keys ------------------------------------
__global__ void hist_kernel(const int* __restrict__ dst_idx,
                            const int* __restrict__ etype) {
    int e = blockIdx.x * 256 + threadIdx.x;   // grid sized exactly EE/256
    int d = __ldg(&dst_idx[e]);
    int r = __ldg(&etype[e]);
    atomicAdd(&g_hist[d * RR + r], 1u);
}

// ---------------- K: 3-stage exclusive scan of g_hist -> g_keyoff -----------
__global__ void scan1_kernel() {
    __shared__ unsigned wsum[8];
    const int tid = threadIdx.x;
    const int base = blockIdx.x * 2048 + tid * 8;
    unsigned v[8];
    unsigned s = 0;
#pragma unroll
    for (int j = 0; j < 8; j++) {
        unsigned x = (base + j < NKEY) ? g_hist[base + j] : 0u;
        v[j] = s;
        s += x;
    }
    const int lane = tid & 31, wid = tid >> 5;
    unsigned t = s;
#pragma unroll
    for (int off = 1; off < 32; off <<= 1) {
        unsigned y = __shfl_up_sync(0xffffffffu, t, off);
        if (lane >= off) t += y;
    }
    if (lane == 31) wsum[wid] = t;
    __syncthreads();
    unsigned wpre = 0;
    for (int w = 0; w < wid; w++) wpre += wsum[w];
    unsigned tpre = wpre + (t - s);
#pragma unroll
    for (int j = 0; j < 8; j++)
        if (base + j < NKEY) g_keyoff[base + j] = tpre + v[j];
    if (tid == 255) g_bsum[blockIdx.x] = tpre + s;
}

__global__ void scan2_kernel(int nb) {
    __shared__ unsigned wsum[8];
    const int tid = threadIdx.x;
    unsigned val = (tid < nb) ? g_bsum[tid] : 0u;
    const int lane = tid & 31, wid = tid >> 5;
    unsigned t = val;
#pragma unroll
    for (int off = 1; off < 32; off <<= 1) {
        unsigned y = __shfl_up_sync(0xffffffffu, t, off);
        if (lane >= off) t += y;
    }
    if (lane == 31) wsum[wid] = t;
    __syncthreads();
    unsigned wpre = 0;
    for (int w = 0; w < wid; w++) wpre += wsum[w];
    unsigned excl = wpre + t - val;
    __syncthreads();
    if (tid < nb) g_bsum[tid] = excl;
}

__global__ void scan3_kernel() {
    int i = blockIdx.x * 256 + threadIdx.x;
    if (i < NKEY) {
        unsigned val = g_keyoff[i] + g_bsum[i >> 11];
        g_keyoff[i] = val;
        g_hist[i] = val;   // scatter cursor
    }
    if (i == 0) g_keyoff[NKEY] = EE;
}

// ---------------- K: scatter edges into sorted record array -----------------
__global__ void scatter_kernel(const int* __restrict__ src_idx,
                               const int* __restrict__ dst_idx,
                               const int* __restrict__ etype) {
    int e = blockIdx.x * 256 + threadIdx.x;
    int s = __ldg(&src_idx[e]);
    int d = __ldg(&dst_idx[e]);
    int r = __ldg(&etype[e]);
    unsigned pos = atomicAdd(&g_hist[d * RR + r], 1u);
    g_rec[pos] = (unsigned)s | ((unsigned)r << 16);
}

// ---------------- GEMM v2 core (device) -------------------------------------
// 128x128 tile, 256 thr = 16tx x 16ty; thread: 8 rows (ty*8..), cols 2tx+32j.
// Wt[i*130+o]: compute-phase LDS.64 conflict-free. Xst[i*132+r]: broadcast.
#define GEMM_SMEM ((128 * 130 + 128 * 132) * 4)

__device__ __forceinline__ void gemm_load_W(float* Wt, const float* __restrict__ W,
                                            int tid) {
#pragma unroll
    for (int kk = 0; kk < 64; kk++) {
        int idx = kk * 256 + tid;
        int o = idx >> 7, i = idx & 127;
        Wt[i * 130 + o] = W[idx];
    }
}

__device__ __forceinline__ void gemm_compute(const float* Wt, const float* Xst,
                                             int tx, int ty,
                                             unsigned long long acc2[8][4]) {
#pragma unroll
    for (int a = 0; a < 8; a++)
#pragma unroll
        for (int b = 0; b < 4; b++) acc2[a][b] = 0ull;
#pragma unroll 4
    for (int i = 0; i < 128; i++) {
        const unsigned long long* wp = (const unsigned long long*)&Wt[i * 130];
        unsigned long long w0 = wp[tx];
        unsigned long long w1 = wp[tx + 16];
        unsigned long long w2 = wp[tx + 32];
        unsigned long long w3 = wp[tx + 48];
        float4 xa = *(const float4*)&Xst[i * 132 + ty * 8];
        float4 xb = *(const float4*)&Xst[i * 132 + ty * 8 + 4];
        float xr[8] = {xa.x, xa.y, xa.z, xa.w, xb.x, xb.y, xb.z, xb.w};
#pragma unroll
        for (int rr = 0; rr < 8; rr++) {
            unsigned long long xv2 = pack2(xr[rr]);
            acc2[rr][0] = fma2(xv2, w0, acc2[rr][0]);
            acc2[rr][1] = fma2(xv2, w1, acc2[rr][1]);
            acc2[rr][2] = fma2(xv2, w2, acc2[rr][2]);
            acc2[rr][3] = fma2(xv2, w3, acc2[rr][3]);
        }
    }
}

__device__ __forceinline__ void gemm_store(unsigned long long acc2[8][4],
                                           const float* __restrict__ bias,
                                           float* __restrict__ Y,
                                           int row0, int tx, int ty) {
    float b0[4], b1[4];
#pragma unroll
    for (int j = 0; j < 4; j++) {
        int o = tx * 2 + 32 * j;
        b0[j] = __ldg(&bias[o]);
        b1[j] = __ldg(&bias[o + 1]);
    }
#pragma unroll
    for (int rr = 0; rr < 8; rr++) {
        int row = row0 + ty * 8 + rr;
        if (row < NN) {
#pragma unroll
            for (int j = 0; j < 4; j++) {
                int o = tx * 2 + 32 * j;
                float lo, hi;
                unpack2(acc2[rr][j], lo, hi);
                float2 ov = make_float2(lo + b0[j], hi + b1[j]);
                *(float2*)&Y[(size_t)row * 128 + o] = ov;
            }
        }
    }
}

// ---------------- K: single GEMM  Y = X @ W^T + b  (optional skip epi) ------
__global__ void __launch_bounds__(256)
gemm128_kernel(const float* __restrict__ X,
               const float* __restrict__ W,
               const float* __restrict__ bias,
               float* __restrict__ Y,
               const float* __restrict__ dsth,
               const float* __restrict__ skipv,
               int mode) {
    extern __shared__ float sm[];
    float* Wt = sm;                  // 128*130
    float* Xst = sm + 128 * 130;     // 128*132
    const int tid = threadIdx.x;
    const int row0 = blockIdx.x * 128;

    gemm_load_W(Wt, W, tid);
#pragma unroll
    for (int kk = 0; kk < 64; kk++) {
        int idx = kk * 256 + tid;
        int rr = idx >> 7, i = idx & 127;
        int row = row0 + rr;
        Xst[i * 132 + rr] = (row < NN) ? X[(size_t)row * 128 + i] : 0.f;
    }
    __syncthreads();

    const int tx = tid & 15, ty = tid >> 4;
    unsigned long long acc2[8][4];
    gemm_compute(Wt, Xst, tx, ty, acc2);

    if (!mode) {
        gemm_store(acc2, bias, Y, row0, tx, ty);
        return;
    }
    float s = skipv[0];
    float alpha = 1.f / (1.f + __expf(-s));
    float beta = 1.f - alpha;
    float b0[4], b1[4];
#pragma unroll
    for (int j = 0; j < 4; j++) {
        int o = tx * 2 + 32 * j;
        b0[j] = __ldg(&bias[o]);
        b1[j] = __ldg(&bias[o + 1]);
    }
#pragma unroll
    for (int rr = 0; rr < 8; rr++) {
        int row = row0 + ty * 8 + rr;
        if (row < NN) {
#pragma unroll
            for (int j = 0; j < 4; j++) {
                int o = tx * 2 + 32 * j;
                float lo, hi;
                unpack2(acc2[rr][j], lo, hi);
                float2 dh = *(const float2*)&dsth[(size_t)row * 128 + o];
                float2 ov = make_float2(alpha * (lo + b0[j]) + beta * dh.x,
                                        alpha * (hi + b1[j]) + beta * dh.y);
                *(float2*)&Y[(size_t)row * 128 + o] = ov;
            }
        }
    }
}

// ---------------- K: fused K/V GEMM — load X tile once, two weight sets -----
__global__ void __launch_bounds__(256)
gemm128_kv_kernel(const float* __restrict__ X,
                  const float* __restrict__ Wk,
                  const float* __restrict__ bk,
                  float* __restrict__ Yk,
                  const float* __restrict__ Wv,
                  const float* __restrict__ bv,
                  float* __restrict__ Yv) {
    extern __shared__ float sm[];
    float* Wt = sm;                  // 128*130
    float* Xst = sm + 128 * 130;     // 128*132
    const int tid = threadIdx.x;
    const int row0 = blockIdx.x * 128;
    const int tx = tid & 15, ty = tid >> 4;

    gemm_load_W(Wt, Wk, tid);
#pragma unroll
    for (int kk = 0; kk < 64; kk++) {
        int idx = kk * 256 + tid;
        int rr = idx >> 7, i = idx & 127;
        int row = row0 + rr;
        Xst[i * 132 + rr] = (row < NN) ? X[(size_t)row * 128 + i] : 0.f;
    }
    __syncthreads();

    unsigned long long acc2[8][4];
    gemm_compute(Wt, Xst, tx, ty, acc2);
    gemm_store(acc2, bk, Yk, row0, tx, ty);

    __syncthreads();               // all Wt reads done before overwrite
    gemm_load_W(Wt, Wv, tid);
    __syncthreads();

    gemm_compute(Wt, Xst, tx, ty, acc2);
    gemm_store(acc2, bv, Yv, row0, tx, ty);
}

// ---------------- K: relation transform (k_rel) -----------------------------
#define RT_SMEM (16384 * 4)
__global__ void reltrans_kernel(const float* __restrict__ ratt) {
    extern __shared__ float sm[];   // [8][8][16][16]
    for (int i = threadIdx.x; i < 16384; i += 256) sm[i] = ratt[i];
    __syncthreads();

    const int lane = threadIdx.x & 31;
    const int wid = blockIdx.x * 8 + (threadIdx.x >> 5);
    const int nwarps = gridDim.x * 8;
    const int ntiles = (NN + 31) / 32;

    for (int tile = wid; tile < ntiles; tile += nwarps) {
        const int n = tile * 32 + lane;
        const bool valid = n < NN;
#pragma unroll 1
        for (int h = 0; h < 8; h++) {
            float kh[16];
            if (valid) {
                const float4* ip = (const float4*)(g_k + (size_t)n * 128 + h * 16);
#pragma unroll
                for (int j = 0; j < 4; j++) {
                    float4 t4 = ip[j];
                    kh[4 * j] = t4.x; kh[4 * j + 1] = t4.y;
                    kh[4 * j + 2] = t4.z; kh[4 * j + 3] = t4.w;
                }
            } else {
#pragma unroll
                for (int j = 0; j < 16; j++) kh[j] = 0.f;
            }
            unsigned long long kd2[16];
#pragma unroll
            for (int d = 0; d < 16; d++) kd2[d] = pack2(kh[d]);

#pragma unroll 1
            for (int r = 0; r < 8; r++) {
                unsigned long long acc2[8];
#pragma unroll
                for (int ep = 0; ep < 8; ep++) acc2[ep] = 0ull;
                const unsigned long long* ap =
                    (const unsigned long long*)(sm + ((r * 8 + h) << 8));
#pragma unroll
                for (int d = 0; d < 16; d++) {
#pragma unroll
                    for (int ep = 0; ep < 8; ep++)
                        acc2[ep] = fma2(kd2[d], ap[d * 8 + ep], acc2[ep]);
                }
                if (valid) {
                    unsigned long long* op = (unsigned long long*)
                        (g_krel + ((size_t)r * NN + n) * 128 + h * 16);
#pragma unroll
                    for (int ep = 0; ep < 8; ep++) op[ep] = acc2[ep];
                }
            }
        }
    }
}

// ---------------- K: fused per-dst attention + aggregation + msg transform --
// Warp per dst node over dst-sorted (key = dst*8+r) edge records.
// smem floats: sM 16384 | spri 64 | sq 8*128 | sex 8*CAP*8 | sden 8*64 | su 8*128
#define FUSE_SMEM ((16384 + 64 + 1024 + 8 * CAP * 8 + 512 + 1024) * 4)
__global__ void __launch_bounds__(256)
fused_edge_kernel(const float* __restrict__ pri,
                  const float* __restrict__ rmsg) {
    extern __shared__ float sm[];
    float* sM = sm;                       // 16384
    float* spri = sm + 16384;             // 64
    const int tid = threadIdx.x;
    const int lane = tid & 31;
    const int w = tid >> 5;
    float* sq   = sm + 16448 + w * 128;
    float* sex  = sm + 16448 + 1024 + w * (CAP * 8);
    float* sden = sm + 16448 + 1024 + 8 * CAP * 8 + w * 64;
    float* su   = sm + 16448 + 1024 + 8 * CAP * 8 + 512 + w * 128;

    for (int i = tid; i < 16384; i += 256) sM[i] = __ldg(&rmsg[i]);
    if (tid < 64) spri[tid] = __ldg(&pri[tid]);
    __syncthreads();

    const int d = blockIdx.x * 8 + w;
    if (d >= NN) return;
    const int h = lane >> 2;
    const int dloc = lane & 3;

    // q row into smem; zero den
    {
        float4 qv = *(const float4*)&g_q[(size_t)d * 128 + lane * 4];
        *(float4*)&sq[lane * 4] = qv;
    }
    sden[lane] = 0.f;
    sden[lane + 32] = 0.f;
    __syncwarp();

    const unsigned start = __ldg(&g_keyoff[d * 8]);
    const unsigned end = __ldg(&g_keyoff[d * 8 + 8]);

    // ---- Pass A: logits -> ex (smem cache) + den -------------------------
    for (unsigned base = start; base < end; base += 32) {
        unsigned e = base + lane;
        if (e < end) {
            unsigned rec = __ldg(&g_rec[e]);
            int s = rec & 0xFFFF;
            int r = (rec >> 16) & 7;
            int idx = (int)(e - start);
            const float4* kp = (const float4*)&g_krel[((size_t)r * NN + s) * 128];
#pragma unroll 2
            for (int hh = 0; hh < 8; hh++) {
                float4 k0 = kp[hh * 4 + 0], k1 = kp[hh * 4 + 1];
                float4 k2 = kp[hh * 4 + 2], k3 = kp[hh * 4 + 3];
                const float4* qp = (const float4*)&sq[hh * 16];
                float4 q0 = qp[0], q1 = qp[1], q2 = qp[2], q3 = qp[3];
                float acc = k0.x * q0.x + k0.y * q0.y + k0.z * q0.z + k0.w * q0.w
                          + k1.x * q1.x + k1.y * q1.y + k1.z * q1.z + k1.w * q1.w
                          + k2.x * q2.x + k2.y * q2.y + k2.z * q2.z + k2.w * q2.w
                          + k3.x * q3.x + k3.y * q3.y + k3.z * q3.z + k3.w * q3.w;
                float ex = __expf(acc * spri[r * 8 + hh] * 0.25f);
                if (idx < CAP) sex[idx * 8 + hh] = ex;
                atomicAdd(&sden[r * 8 + hh], ex);
            }
        }
    }
    __syncwarp();

    // ---- coef = present ? invn/den : 0 (written back into sden) -----------
    {
        float den0 = sden[lane];
        float den1 = sden[lane + 32];
        unsigned flag = 0;
        if (lane < 8) {
            unsigned rs = __ldg(&g_keyoff[d * 8 + lane]);
            unsigned re = __ldg(&g_keyoff[d * 8 + lane + 1]);
            flag = (re > rs) ? 1u : 0u;
        }
        unsigned pm = __ballot_sync(0xffffffffu, flag != 0);
        int cnt = __popc(pm);
        float invn = 1.f / (float)(cnt > 0 ? cnt : 1);
        int r0 = lane >> 3, r1 = (lane + 32) >> 3;
        float c0 = ((pm >> r0) & 1) ? invn / den0 : 0.f;
        float c1 = ((pm >> r1) & 1) ? invn / den1 : 0.f;
        __syncwarp();
        sden[lane] = c0;
        sden[lane + 32] = c1;
    }
    __syncwarp();

    // ---- Pass B: per-r weighted v accumulation + rel_msg transform --------
    float4 o4 = make_float4(0.f, 0.f, 0.f, 0.f);
#pragma unroll 1
    for (int r = 0; r < 8; r++) {
        unsigned rs = __ldg(&g_keyoff[d * 8 + r]);
        unsigned re = __ldg(&g_keyoff[d * 8 + r + 1]);
        if (rs == re) continue;
        float4 u4 = make_float4(0.f, 0.f, 0.f, 0.f);
#pragma unroll 2
        for (unsigned e = rs; e < re; e++) {
            unsigned idx = e - start;
            unsigned rec = __ldg(&g_rec[e]);   // warp-uniform broadcast load
            int s = rec & 0xFFFF;
            float wgt;
            if (idx < CAP) {
                wgt = sex[idx * 8 + h];
            } else {
                const float* kq = &g_krel[((size_t)r * NN + s) * 128 + h * 16];
                const float* qq = &sq[h * 16];
                float acc = 0.f;
#pragma unroll
                for (int dd = 0; dd < 16; dd++) acc += kq[dd] * qq[dd];
                wgt = __expf(acc * spri[r * 8 + h] * 0.25f);
            }
            float4 vv = *(const float4*)&g_v[(size_t)s * 128 + lane * 4];
            u4.x += wgt * vv.x; u4.y += wgt * vv.y;
            u4.z += wgt * vv.z; u4.w += wgt * vv.w;
        }
        float c = sden[r * 8 + h];
        u4.x *= c; u4.y *= c; u4.z *= c; u4.w *= c;
        __syncwarp();
        *(float4*)&su[lane * 4] = u4;
        __syncwarp();
        const float* mp = &sM[((r * 8 + h) * 16) * 16 + dloc * 4];
#pragma unroll
        for (int dd = 0; dd < 16; dd++) {
            float uv = su[h * 16 + dd];
            float4 m4 = *(const float4*)&mp[dd * 16];
            o4.x += uv * m4.x; o4.y += uv * m4.y;
            o4.z += uv * m4.z; o4.w += uv * m4.w;
        }
    }
    *(float4*)&g_t[(size_t)d * 128 + lane * 4] = o4;
}

// ---------------- host ------------------------------------------------------
extern "C" void kernel_launch(void* const* d_in, const int* in_sizes, int n_in,
                              void* d_out, int out_size) {
    const float* src_h   = (const float*)d_in[0];
    const float* dst_h   = (const float*)d_in[1];
    const float* Wk      = (const float*)d_in[2];
    const float* bk      = (const float*)d_in[3];
    const float* Wq      = (const float*)d_in[4];
    const float* bq      = (const float*)d_in[5];
    const float* Wv      = (const float*)d_in[6];
    const float* bv      = (const float*)d_in[7];
    const float* Wa      = (const float*)d_in[8];
    const float* ba      = (const float*)d_in[9];
    const float* rel_pri = (const float*)d_in[10];
    const float* rel_att = (const float*)d_in[11];
    const float* rel_msg = (const float*)d_in[12];
    const float* skip    = (const float*)d_in[13];
    const int* src_idx   = (const int*)d_in[14];
    const int* dst_idx   = (const int*)d_in[15];
    const int* edge_type = (const int*)d_in[16];
    float* out = (float*)d_out;

    cudaFuncSetAttribute(gemm128_kernel,
                         cudaFuncAttributeMaxDynamicSharedMemorySize, GEMM_SMEM);
    cudaFuncSetAttribute(gemm128_kv_kernel,
                         cudaFuncAttributeMaxDynamicSharedMemorySize, GEMM_SMEM);
    cudaFuncSetAttribute(reltrans_kernel,
                         cudaFuncAttributeMaxDynamicSharedMemorySize, RT_SMEM);
    cudaFuncSetAttribute(fused_edge_kernel,
                         cudaFuncAttributeMaxDynamicSharedMemorySize, FUSE_SMEM);

    float *p_q, *p_k, *p_v, *p_t;
    cudaGetSymbolAddress((void**)&p_q, g_q);
    cudaGetSymbolAddress((void**)&p_k, g_k);
    cudaGetSymbolAddress((void**)&p_v, g_v);
    cudaGetSymbolAddress((void**)&p_t, g_t);

    const int gblocks = (NN + 127) / 128;        // 391
    const int kblocks = (NKEY + 255) / 256;      // 1563
    const int eblocks = EE / 256;                // 6250
    const int sblocks = (NKEY + 2047) / 2048;    // 196

    // sort pipeline (independent of projections)
    zero_hist_kernel<<<kblocks, 256>>>();
    hist_kernel<<<eblocks, 256>>>(dst_idx, edge_type);
    scan1_kernel<<<sblocks, 256>>>();
    scan2_kernel<<<1, 256>>>(sblocks);
    scan3_kernel<<<kblocks, 256>>>();
    scatter_kernel<<<eblocks, 256>>>(src_idx, dst_idx, edge_type);

    // projections (k+v fused: one src_h read)
    gemm128_kv_kernel<<<gblocks, 256, GEMM_SMEM>>>(src_h, Wk, bk, p_k, Wv, bv, p_v);
    gemm128_kernel<<<gblocks, 256, GEMM_SMEM>>>(dst_h, Wq, bq, p_q, nullptr, nullptr, 0);
    reltrans_kernel<<<196, 256, RT_SMEM>>>(rel_att);

    // fused edge pipeline
    fused_edge_kernel<<<(NN + 7) / 8, 256, FUSE_SMEM>>>(rel_pri, rel_msg);

    // output projection + skip
    gemm128_kernel<<<gblocks, 256, GEMM_SMEM>>>(p_t, Wa, ba, out, dst_h, skip, 1);
}